// round 11
// baseline (speedup 1.0000x reference)
#include <cuda_runtime.h>

#define DD 512
#define NN 128
#define TPB 512
#define TINYF 1e-30f

// ---- packed f32x2 helpers (Blackwell FFMA2) ----
__device__ __forceinline__ unsigned long long fma2(unsigned long long a,
                                                   unsigned long long b,
                                                   unsigned long long c) {
    unsigned long long d;
    asm("fma.rn.f32x2 %0, %1, %2, %3;" : "=l"(d) : "l"(a), "l"(b), "l"(c));
    return d;
}
__device__ __forceinline__ float lo2(unsigned long long v) {
    return __uint_as_float((unsigned)v);
}
__device__ __forceinline__ float hi2(unsigned long long v) {
    return __uint_as_float((unsigned)(v >> 32));
}
__device__ __forceinline__ unsigned long long pack2(float x, float y) {
    unsigned long long d;
    asm("mov.b64 %0, {%1, %2};" : "=l"(d) : "f"(x), "f"(y));
    return d;
}

// Woodbury top-block sampler, ONE barrier per step.
//
// Thread t: row r = t>>2, col slice [32h, 32h+32), h = t&3 — the 4 slice
// threads of a row share a warp, so q-assembly is 2 shfl-xor (no LDS/barrier).
//
// iter i (entering: sh_q[i&1]=q_i, sh_wred=warp partials of up_i.q_i,
//         qr reg = q_i[r], up_{i+1} staged in the sh_up ring):
//   post-barrier: red_i = sum16(sh_wred) -> decision_i -> pivinv_i (redundant)
//   fused loop:   rb2 += (qr*pivinv_i)*q_i[slice];  acc += rb2*up_{i+1}[slice]
//   2 shfls:      q_{i+1}[r]; h==0 stores sh_q[(i+1)&1][r]
//   5 shfls:      warp partial of up_{i+1}.q_{i+1} -> sh_wred[wid]
//   prefetch:     tid<128 STS up_{i+2}, LDG up_{i+3}
//   __syncthreads (the only barrier)
__global__ __launch_bounds__(TPB, 1)
void slater_sampler_kernel(const float* __restrict__ P,
                           const float* __restrict__ uin,
                           float* __restrict__ out,
                           int out_size)
{
    __shared__ __align__(16) float sh_up[3][NN];
    __shared__ __align__(16) float sh_q[2][NN];
    __shared__ __align__(16) float sh_wred[16];
    __shared__ __align__(16) float sh_u[NN];

    const int tid  = threadIdx.x;
    const int lane = tid & 31;
    const int wid  = tid >> 5;
    const int r    = tid >> 2;      // owned row
    const int h    = tid & 3;       // col-slice id
    const int cbase = 32 * h;
    const int pos_base = NN * DD;

    // ---- init output: cond_probs = 0, positions = -1 ----
    {
        int n4 = out_size >> 2;
        float4* o4 = (float4*)out;
        for (int idx = tid; idx < n4; idx += TPB) {
            int base = idx * 4;
            float4 v;
            v.x = (base + 0 < pos_base) ? 0.0f : -1.0f;
            v.y = (base + 1 < pos_base) ? 0.0f : -1.0f;
            v.z = (base + 2 < pos_base) ? 0.0f : -1.0f;
            v.w = (base + 3 < pos_base) ? 0.0f : -1.0f;
            o4[idx] = v;
        }
        for (int idx = (n4 << 2) + tid; idx < out_size; idx += TPB)
            out[idx] = (idx < pos_base) ? 0.0f : -1.0f;
    }

    float pfreg = 0.0f;
    if (tid < NN) {
        sh_u[tid]     = uin[tid];
        sh_up[0][tid] = P[tid];              // up_0
        sh_up[1][tid] = P[NN + tid];         // up_1
        pfreg         = P[2 * NN + tid];     // up_2 (STS'd at iter 0)
        sh_q[0][tid]  = P[tid];              // q_0 = up_0
    }

    // B slice = identity (16 packed f32x2 = 32 regs)
    unsigned long long rb2[16];
#pragma unroll
    for (int m = 0; m < 16; ++m) {
        unsigned long long v = 0ULL;
        int c0 = cbase + 2 * m;
        if (c0 == r)          v = 0x000000003f800000ULL;
        else if (c0 + 1 == r) v = 0x3f80000000000000ULL;
        rb2[m] = v;
    }
    __syncthreads();

    // qr = q_0[r]; initial sh_wred = warp partials of up_0 . q_0
    float qr = sh_up[0][r];
    {
        float contrib = (h == 0) ? qr * qr : 0.0f;
#pragma unroll
        for (int o = 16; o; o >>= 1)
            contrib += __shfl_xor_sync(0xffffffffu, contrib, o);
        if (lane == 0) sh_wred[wid] = contrib;
    }
    __syncthreads();

    const bool write_pos = (pos_base + NN) <= out_size;

    // redundant per-thread sampler state (identical across all threads)
    float ratio = 1.0f, cumul = 0.0f;
    int   k = 0;

    for (int i = 0; i < DD; ++i) {
        // ---- post-barrier scalar phase: red_i, decision_i (redundant) ----
        float red;
        {
            const float4* w4 = (const float4*)sh_wred;
            float4 w0 = w4[0], w1 = w4[1], w2 = w4[2], w3 = w4[3];
            red = (((w0.x + w0.y) + (w0.z + w0.w)) + ((w1.x + w1.y) + (w1.z + w1.w)))
                + (((w2.x + w2.y) + (w2.z + w2.w)) + ((w3.x + w3.y) + (w3.z + w3.w)));
        }
        float s = 1.0f - red;
        int last_allowed = DD - NN + k;
        float p  = -(s - 1.0f) * ratio;
        float uk = sh_u[k];
        bool occupy = ((cumul + p) >= uk) || (i == last_allowed);

        float pivot = occupy ? (s - 1.0f) : s;
        if (fabsf(pivot) < TINYF) pivot = TINYF;
        float pivinv = 1.0f / pivot;

        if (tid == 0) {
            out[k * DD + i] = p;
            if (occupy && write_pos) out[pos_base + k] = (float)i;
        }
        if (occupy) { ratio = 1.0f; cumul = 0.0f; ++k; }
        else        { ratio *= s;  cumul += p; }

        if (k == NN) break;   // all particles placed; remaining rows dropped

        // ---- fused: rank-1(i) + matvec(i+1) ----
        const float* q   = sh_q[i & 1];
        const float* upn = sh_up[(i + 1) % 3];
        float scale = qr * pivinv;
        unsigned long long s2 = pack2(scale, scale);
        const ulonglong2* q2 = (const ulonglong2*)(q + cbase);
        const ulonglong2* u2 = (const ulonglong2*)(upn + cbase);
        unsigned long long a0 = 0, a1 = 0, a2 = 0, a3 = 0;
#pragma unroll
        for (int j = 0; j < 4; ++j) {
            ulonglong2 qa = q2[2 * j];
            ulonglong2 qb = q2[2 * j + 1];
            ulonglong2 ua = u2[2 * j];
            ulonglong2 ub = u2[2 * j + 1];
            rb2[4 * j + 0] = fma2(s2, qa.x, rb2[4 * j + 0]);
            a0 = fma2(rb2[4 * j + 0], ua.x, a0);
            rb2[4 * j + 1] = fma2(s2, qa.y, rb2[4 * j + 1]);
            a1 = fma2(rb2[4 * j + 1], ua.y, a1);
            rb2[4 * j + 2] = fma2(s2, qb.x, rb2[4 * j + 2]);
            a2 = fma2(rb2[4 * j + 2], ub.x, a2);
            rb2[4 * j + 3] = fma2(s2, qb.y, rb2[4 * j + 3]);
            a3 = fma2(rb2[4 * j + 3], ub.y, a3);
        }
        float qn = ((lo2(a0) + hi2(a0)) + (lo2(a1) + hi2(a1)))
                 + ((lo2(a2) + hi2(a2)) + (lo2(a3) + hi2(a3)));

        // ---- q-assembly: sum the 4 slice partials (same warp) ----
        qn += __shfl_xor_sync(0xffffffffu, qn, 1);
        qn += __shfl_xor_sync(0xffffffffu, qn, 2);
        if (h == 0) sh_q[(i + 1) & 1][r] = qn;
        qr = qn;

        // ---- warp partial of up_{i+1} . q_{i+1} ----
        float contrib = (h == 0) ? upn[r] * qn : 0.0f;
#pragma unroll
        for (int o = 16; o; o >>= 1)
            contrib += __shfl_xor_sync(0xffffffffu, contrib, o);
        if (lane == 0) sh_wred[wid] = contrib;

        // ---- prefetch ring: STS up_{i+2}, LDG up_{i+3} ----
        if (tid < NN) {
            if (i + 2 < DD) sh_up[(i + 2) % 3][tid] = pfreg;
            if (i + 3 < DD) pfreg = P[(size_t)(i + 3) * NN + tid];
        }

        __syncthreads();   // the ONLY barrier per step
    }
}

extern "C" void kernel_launch(void* const* d_in, const int* in_sizes, int n_in,
                              void* d_out, int out_size)
{
    const float* P = (const float*)d_in[0];   // (512, 128) row-major
    const float* u = (const float*)d_in[1];   // (128,)
    float* out = (float*)d_out;
    slater_sampler_kernel<<<1, TPB>>>(P, u, out, out_size);
}

// round 12
// speedup vs baseline: 3.5604x; 3.5604x over previous
#include <cuda_runtime.h>

#define DD 512
#define NN 128
#define TPB 512
#define TINYF 1e-30f

// ---- packed f32x2 helpers (Blackwell FFMA2) ----
__device__ __forceinline__ unsigned long long fma2(unsigned long long a,
                                                   unsigned long long b,
                                                   unsigned long long c) {
    unsigned long long d;
    asm("fma.rn.f32x2 %0, %1, %2, %3;" : "=l"(d) : "l"(a), "l"(b), "l"(c));
    return d;
}
__device__ __forceinline__ float lo2(unsigned long long v) {
    return __uint_as_float((unsigned)v);
}
__device__ __forceinline__ float hi2(unsigned long long v) {
    return __uint_as_float((unsigned)(v >> 32));
}
__device__ __forceinline__ unsigned long long pack2(float x, float y) {
    unsigned long long d;
    asm("mov.b64 %0, {%1, %2};" : "=l"(d) : "f"(x), "f"(y));
    return d;
}

// Woodbury top-block sampler — round-4 skeleton with de-redundantized phases.
//
// Thread t: row r = t&127, col slice [32h,32h+32), h = t>>7; rb2[16] regs.
//
// Phase A (pre-B_mid):
//   warps 0-3 : row = 32*wid+lane; q[row] = 4-way sum of sh_part; sh_q[row];
//               contrib = up_i[row]*q[row]; 5-shfl reduce -> sh_wred[wid]
//   warps 4-7 : STS up_{i+1} from pfreg; LDG up_{i+2} -> pfreg
// B_mid
// Phase B (all threads):
//   red = sum4(sh_wred); decision (redundant, per-thread state); qr = sh_q[r]
//   fused: rb2 += (qr*pivinv)*q[slice]; acc += rb2*up_{i+1}[slice]
//   sh_part[tid] = acc-sum (partial of q_{i+1})
// B_end
__global__ __launch_bounds__(TPB, 1)
void slater_sampler_kernel(const float* __restrict__ P,
                           const float* __restrict__ uin,
                           float* __restrict__ out,
                           int out_size)
{
    __shared__ __align__(16) float sh_up[3][NN];
    __shared__ __align__(16) float sh_part[TPB];
    __shared__ __align__(16) float sh_q[NN];
    __shared__ __align__(16) float sh_wred[4];
    __shared__ __align__(16) float sh_u[NN];

    const int tid  = threadIdx.x;
    const int lane = tid & 31;
    const int wid  = tid >> 5;
    const int r    = tid & 127;
    const int h    = tid >> 7;
    const int cbase = 32 * h;
    const int pos_base = NN * DD;

    // ---- init output: cond_probs = 0, positions = -1 ----
    {
        int n4 = out_size >> 2;
        float4* o4 = (float4*)out;
        for (int idx = tid; idx < n4; idx += TPB) {
            int base = idx * 4;
            float4 v;
            v.x = (base + 0 < pos_base) ? 0.0f : -1.0f;
            v.y = (base + 1 < pos_base) ? 0.0f : -1.0f;
            v.z = (base + 2 < pos_base) ? 0.0f : -1.0f;
            v.w = (base + 3 < pos_base) ? 0.0f : -1.0f;
            o4[idx] = v;
        }
        for (int idx = (n4 << 2) + tid; idx < out_size; idx += TPB)
            out[idx] = (idx < pos_base) ? 0.0f : -1.0f;
    }

    if (tid < NN) {
        sh_u[tid]     = uin[tid];
        sh_up[0][tid] = P[tid];              // up_0
    }
    float pfreg = 0.0f;
    if (tid >= 128 && tid < 256)
        pfreg = P[NN + (tid - 128)];         // up_1 (STS'd at iter 0)

    // Initial partials of q_0 = up_0: thread (r, h=0) carries up_0[r].
    sh_part[tid] = (h == 0) ? P[r] : 0.0f;

    // B slice = identity (16 packed f32x2 = 32 regs)
    unsigned long long rb2[16];
#pragma unroll
    for (int m = 0; m < 16; ++m) {
        unsigned long long v = 0ULL;
        int c0 = cbase + 2 * m;
        if (c0 == r)          v = 0x000000003f800000ULL;
        else if (c0 + 1 == r) v = 0x3f80000000000000ULL;
        rb2[m] = v;
    }
    __syncthreads();

    const bool write_pos = (pos_base + NN) <= out_size;

    // redundant per-thread sampler state (identical across all threads)
    float ratio = 1.0f, cumul = 0.0f;
    int   k = 0;

    for (int i = 0; i < DD; ++i) {
        // ================= PHASE A =================
        if (wid < 4) {
            int row = (wid << 5) | lane;
            float q = (sh_part[row] + sh_part[row + 128])
                    + (sh_part[row + 256] + sh_part[row + 384]);
            sh_q[row] = q;
            float contrib = sh_up[i % 3][row] * q;
#pragma unroll
            for (int o = 16; o; o >>= 1)
                contrib += __shfl_xor_sync(0xffffffffu, contrib, o);
            if (lane == 0) sh_wred[wid] = contrib;
        } else if (wid < 8) {
            int idx = tid - 128;
            if (i + 1 < DD) sh_up[(i + 1) % 3][idx] = pfreg;
            if (i + 2 < DD) pfreg = P[(size_t)(i + 2) * NN + idx];
        }
        __syncthreads();   // B_mid

        // ================= PHASE B (all threads) =================
        float4 w = *(const float4*)sh_wred;
        float red = (w.x + w.y) + (w.z + w.w);
        float qr = sh_q[r];

        float s = 1.0f - red;
        int last_allowed = DD - NN + k;
        float p  = -(s - 1.0f) * ratio;
        float uk = sh_u[k];
        bool occupy = ((cumul + p) >= uk) || (i == last_allowed);

        float pivot = occupy ? (s - 1.0f) : s;
        if (fabsf(pivot) < TINYF) pivot = TINYF;
        float pivinv = 1.0f / pivot;

        if (tid == 0) {
            out[k * DD + i] = p;
            if (occupy && write_pos) out[pos_base + k] = (float)i;
        }
        if (occupy) { ratio = 1.0f; cumul = 0.0f; ++k; }
        else        { ratio *= s;  cumul += p; }

        if (k == NN) break;   // all particles placed

        // ---- fused: rank-1(i) + matvec(i+1) over this thread's slice ----
        const float* upn = sh_up[(i + 1) % 3];
        float scale = qr * pivinv;
        unsigned long long s2 = pack2(scale, scale);
        const ulonglong2* q2 = (const ulonglong2*)(sh_q + cbase);
        const ulonglong2* u2 = (const ulonglong2*)(upn + cbase);
        unsigned long long a0 = 0, a1 = 0, a2 = 0, a3 = 0;
#pragma unroll
        for (int j = 0; j < 4; ++j) {
            ulonglong2 qa = q2[2 * j];
            ulonglong2 qb = q2[2 * j + 1];
            ulonglong2 ua = u2[2 * j];
            ulonglong2 ub = u2[2 * j + 1];
            rb2[4 * j + 0] = fma2(s2, qa.x, rb2[4 * j + 0]);
            a0 = fma2(rb2[4 * j + 0], ua.x, a0);
            rb2[4 * j + 1] = fma2(s2, qa.y, rb2[4 * j + 1]);
            a1 = fma2(rb2[4 * j + 1], ua.y, a1);
            rb2[4 * j + 2] = fma2(s2, qb.x, rb2[4 * j + 2]);
            a2 = fma2(rb2[4 * j + 2], ub.x, a2);
            rb2[4 * j + 3] = fma2(s2, qb.y, rb2[4 * j + 3]);
            a3 = fma2(rb2[4 * j + 3], ub.y, a3);
        }
        sh_part[tid] = ((lo2(a0) + hi2(a0)) + (lo2(a1) + hi2(a1)))
                     + ((lo2(a2) + hi2(a2)) + (lo2(a3) + hi2(a3)));

        __syncthreads();   // B_end
    }
}

extern "C" void kernel_launch(void* const* d_in, const int* in_sizes, int n_in,
                              void* d_out, int out_size)
{
    const float* P = (const float*)d_in[0];   // (512, 128) row-major
    const float* u = (const float*)d_in[1];   // (128,)
    float* out = (float*)d_out;
    slater_sampler_kernel<<<1, TPB>>>(P, u, out, out_size);
}